// round 9
// baseline (speedup 1.0000x reference)
#include <cuda_runtime.h>
#include <math.h>
#include <stdint.h>

// Problem constants
#define L_SEQ 2048
#define B_SZ  32
#define DIN   128
#define DST   512

// Scratch (device globals per allocation rules)
__device__ float g_pre[L_SEQ * B_SZ * DST];   // [l][b][h]   128 MB
__device__ float g_hs [L_SEQ * B_SZ * DST];   // [l][b][h]   128 MB
__device__ float g_xT [L_SEQ * B_SZ * DIN];   // [l][b][d]    32 MB

union F4U  { float4 f4; ulonglong2 u2; };
union U64F { unsigned long long u; float2 f; };

__device__ __forceinline__ void ffma2(unsigned long long& acc,
                                      unsigned long long a,
                                      unsigned long long b) {
    asm volatile("fma.rn.f32x2 %0, %1, %2, %0;" : "+l"(acc) : "l"(a), "l"(b));
}

__device__ __forceinline__ uint32_t smem_u32(const void* p) {
    return (uint32_t)__cvta_generic_to_shared(p);
}

// ---------------------------------------------------------------------------
// Kernel 0: transpose x[b][d][l] -> xT[l][b*128+d].
// ---------------------------------------------------------------------------
__global__ void __launch_bounds__(256) k_xT(const float* __restrict__ x) {
    __shared__ float sm[32 * 33];
    const int l0  = blockIdx.x * 32;
    const int bd0 = blockIdx.y * 32;
    const int t   = threadIdx.x;
    for (int i = t; i < 1024; i += 256) {
        int r = i >> 5, c = i & 31;
        sm[r * 33 + c] = x[(size_t)(bd0 + r) * L_SEQ + l0 + c];
    }
    __syncthreads();
    for (int i = t; i < 1024; i += 256) {
        int r = i >> 5, c = i & 31;
        g_xT[(size_t)(l0 + r) * (B_SZ * DIN) + bd0 + c] = sm[c * 33 + r];
    }
}

// ---------------------------------------------------------------------------
// Kernel 1: pre[l][b][h]. 2 timesteps per block (W staged once).
// ---------------------------------------------------------------------------
#define PRE_SMEM ((128 * 257 + 128 * 36) * 4)

__global__ void __launch_bounds__(512) k_pre(const float* __restrict__ Wih,
                                             const float* __restrict__ bih,
                                             const float* __restrict__ bhh) {
    extern __shared__ float sm[];
    float* w_s = sm;               // [128 d][257]
    float* x_s = sm + 128 * 257;   // [128 d][36]

    const int lbase = blockIdx.x * 2;
    const int h0 = blockIdx.y * 256;
    const int t  = threadIdx.x;

    for (int idx = t; idx < 256 * 128; idx += 512) {
        int d = idx & 127, hh = idx >> 7;
        w_s[d * 257 + hh] = Wih[(size_t)(h0 + hh) * DIN + d];
    }

    const int tx = t & 63;
    const int b0 = (t >> 6) * 4;

    float bias[4];
#pragma unroll
    for (int j = 0; j < 4; j++)
        bias[j] = bih[h0 + tx + 64 * j] + bhh[h0 + tx + 64 * j];

    for (int l2 = 0; l2 < 2; l2++) {
        const int l = lbase + l2;
        __syncthreads();   // w_s ready (iter 0) / x_s consumers done (iter 1)
        for (int idx = t; idx < B_SZ * DIN; idx += 512) {
            int d = idx & 127, b = idx >> 7;
            x_s[d * 36 + b] = g_xT[(size_t)l * (B_SZ * DIN) + b * DIN + d];
        }
        __syncthreads();

        unsigned long long acc[2][4];
#pragma unroll
        for (int m = 0; m < 2; m++)
#pragma unroll
            for (int b = 0; b < 4; b++) acc[m][b] = 0ull;

#pragma unroll 4
        for (int k = 0; k < 128; k++) {
            const float* wr = w_s + k * 257 + tx;
            U64F p0, p1;
            p0.f.x = wr[0];   p0.f.y = wr[64];
            p1.f.x = wr[128]; p1.f.y = wr[192];
            F4U xv; xv.f4 = *(const float4*)(x_s + k * 36 + b0);
            float xs[4] = {xv.f4.x, xv.f4.y, xv.f4.z, xv.f4.w};
#pragma unroll
            for (int b = 0; b < 4; b++) {
                U64F d2; d2.f.x = xs[b]; d2.f.y = xs[b];
                ffma2(acc[0][b], p0.u, d2.u);
                ffma2(acc[1][b], p1.u, d2.u);
            }
        }

#pragma unroll
        for (int b = 0; b < 4; b++) {
            float* pr = g_pre + ((size_t)l * B_SZ + b0 + b) * DST + h0 + tx;
            U64F u0, u1; u0.u = acc[0][b]; u1.u = acc[1][b];
            pr[0]   = u0.f.x + bias[0];
            pr[64]  = u0.f.y + bias[1];
            pr[128] = u1.f.x + bias[2];
            pr[192] = u1.f.y + bias[3];
        }
    }
}

// ---------------------------------------------------------------------------
// Kernel 2: recurrent scan. 16 clusters x 8 CTAs x 576 threads; 2 batches per
// cluster. Flag-based sync: producers push h (coalesced 128B warp-stores) then
// ONE st.release.cluster flag per peer carrying the step number; consumers
// spin on a LOCAL smem word with ld.acquire (cheap fast path). No mbarriers.
//   warps 0-15: compute (W in regs, broadcast LDS, FFMA2)
//   warps 16,17: tail for batch 0 / 1 (lane u owns rows u, u+32)
// red[] parity double-buffered; phase named-bars alternate by step parity.
// ---------------------------------------------------------------------------
__global__ void __launch_bounds__(576, 1) __cluster_dims__(8, 1, 1)
k_rnn(const float* __restrict__ Whh) {
    __shared__ float hbuf[2][2 * DST];        // [parity][batch*512+h]
    __shared__ float red[2][2][64][9];        // [parity][batch][row][kslice]
    __shared__ uint32_t flag[2][8];           // [batch][src]: step# whose data arrived

    const int t    = threadIdx.x;
    const int warp = t >> 5;
    const int lane = t & 31;
    uint32_t rank;
    asm("mov.u32 %0, %%cluster_ctarank;" : "=r"(rank));
    const int cl = blockIdx.x >> 3;           // cluster id 0..15

    // compute-warp constants + register W
    const int rg  = warp & 1;
    const int kw  = warp >> 1;                // K slice / source CTA 0..7
    const int row = rg * 32 + lane;           // local row 0..63
    const int ks  = kw * 64;
    F4U w[16];
    if (t < 512) {
        const float4* wp = (const float4*)(Whh + (size_t)(rank * 64 + row) * DST + ks);
#pragma unroll
        for (int i = 0; i < 16; i++) w[i].f4 = wp[i];
    }

    // h_{-1} = 0 lives in parity buffer 1; flags start at 0
    for (int i = t; i < 2 * DST; i += 576) hbuf[1][i] = 0.f;
    if (t < 16) flag[t >> 3][t & 7] = 0u;
    __syncthreads();
    asm volatile("barrier.cluster.arrive.aligned;" ::: "memory");
    asm volatile("barrier.cluster.wait.aligned;" ::: "memory");

    const uint32_t hbase = smem_u32(&hbuf[0][0]);
    uint32_t peer_h[8];
#pragma unroll
    for (int p = 0; p < 8; p++)
        asm("mapa.shared::cluster.u32 %0, %1, %2;" : "=r"(peer_h[p]) : "r"(hbase), "r"(p));

    if (t < 512) {
        // ================= COMPUTE WARPS =================
        const uint32_t fa0 = smem_u32(&flag[0][kw]);
        const uint32_t fa1 = smem_u32(&flag[1][kw]);

        for (int l = 0; l < L_SEQ; l++) {
            const int prev = (l & 1) ^ 1;
            const int rbuf = l & 1;
            const float* hbp = hbuf[prev];

#pragma unroll
            for (int b = 0; b < 2; b++) {
                if (l > 0) {
                    uint32_t fa = b ? fa1 : fa0;
                    asm volatile(
                        "{\n\t.reg .pred P;\n\t.reg .u32 V;\n"
                        "SPIN%=:\n\t"
                        "ld.acquire.cluster.shared::cta.u32 V, [%0];\n\t"
                        "setp.lt.s32 P, V, %1;\n\t"
                        "@P bra SPIN%=;\n\t}"
                        :: "r"(fa), "r"(l) : "memory");
                }
                const float4* hp = (const float4*)(hbp + b * DST + ks);
                unsigned long long a0 = 0ull, a1 = 0ull;
#pragma unroll
                for (int i = 0; i < 16; i++) {
                    F4U hv; hv.f4 = hp[i];    // broadcast LDS
                    ffma2(a0, hv.u2.x, w[i].u2.x);
                    ffma2(a1, hv.u2.y, w[i].u2.y);
                }
                U64F u0, u1; u0.u = a0; u1.u = a1;
                red[rbuf][b][row][kw] = u0.f.x + u0.f.y + u1.f.x + u1.f.y;
                asm volatile("bar.arrive %0, 544;"
                             :: "r"(1 + b * 2 + (l & 1)) : "memory");
            }
        }
    } else {
        // ================= TAIL WARPS (one per batch) =================
        const int tb = warp - 16;             // my batch 0/1
        const int u  = lane;                  // rows u and u+32
        const size_t oi0 = (size_t)(cl * 2 + tb) * DST + rank * 64 + u;
        const uint32_t po0 = (uint32_t)((tb * DST + (int)rank * 64 + u) * 4);
        // lane u<8: address of flag[tb][rank] inside peer u's smem
        uint32_t fladdr = 0;
        if (u < 8) {
            uint32_t local = smem_u32(&flag[tb][rank]);
            asm("mapa.shared::cluster.u32 %0, %1, %2;" : "=r"(fladdr) : "r"(local), "r"(u));
        }

        for (int l = 0; l < L_SEQ; l++) {
            const int cur  = l & 1;
            const int rbuf = l & 1;
            float pv0 = __ldg(g_pre + (size_t)l * (B_SZ * DST) + oi0);
            float pv1 = __ldg(g_pre + (size_t)l * (B_SZ * DST) + oi0 + 32);

            asm volatile("bar.sync %0, 544;"
                         :: "r"(1 + tb * 2 + (l & 1)) : "memory");

            float s0 = pv0, s1 = pv1;
#pragma unroll
            for (int k2 = 0; k2 < 8; k2++) {
                s0 += red[rbuf][tb][u][k2];
                s1 += red[rbuf][tb][u + 32][k2];
            }
            float hv0 = tanhf(s0), hv1 = tanhf(s1);
            g_hs[(size_t)l * (B_SZ * DST) + oi0]      = hv0;
            g_hs[(size_t)l * (B_SZ * DST) + oi0 + 32] = hv1;

            if (l < L_SEQ - 1) {
                uint32_t off0 = (uint32_t)(cur * 2 * DST * 4) + po0;
#pragma unroll
                for (int p = 0; p < 8; p++) {
                    asm volatile("st.shared::cluster.f32 [%0], %1;"
                                 :: "r"(peer_h[p] + off0), "f"(hv0) : "memory");
                    asm volatile("st.shared::cluster.f32 [%0], %1;"
                                 :: "r"(peer_h[p] + off0 + 128), "f"(hv1) : "memory");
                }
                __syncwarp();   // all lanes' pushes happen-before the flags
                if (u < 8)
                    asm volatile("st.release.cluster.shared::cluster.b32 [%0], %1;"
                                 :: "r"(fladdr), "r"(l + 1) : "memory");
            }
        }
    }

    // No CTA may exit while peers could still touch its smem.
    asm volatile("barrier.cluster.arrive.aligned;" ::: "memory");
    asm volatile("barrier.cluster.wait.aligned;" ::: "memory");
}

// ---------------------------------------------------------------------------
// Kernel 3: y[lb][o] = tanh(b_fc[o] + sum_k hs[lb][k] * W_fc[o][k])
// ---------------------------------------------------------------------------
#define OUT_SMEM ((128 * 132 + 128 * 68) * 4)

__global__ void __launch_bounds__(512) k_out(const float* __restrict__ Wfc,
                                             const float* __restrict__ bfc,
                                             float* __restrict__ y) {
    extern __shared__ float sm[];
    float* w_s = sm;               // [128 kk][132]
    float* a_s = sm + 128 * 132;   // [128 kk][68]

    const int t = threadIdx.x;
    const size_t base = (size_t)blockIdx.x * 64;
    const int tx  = t & 31;
    const int lb0 = (t >> 5) * 4;

    unsigned long long acc[2][4];
#pragma unroll
    for (int m = 0; m < 2; m++)
#pragma unroll
        for (int b = 0; b < 4; b++) acc[m][b] = 0ull;

    for (int kc = 0; kc < 4; kc++) {
        __syncthreads();
        for (int idx = t; idx < 128 * 128; idx += 512) {
            int kk = idx & 127, o = idx >> 7;
            w_s[kk * 132 + o] = Wfc[(size_t)o * DST + kc * 128 + kk];
        }
        for (int idx = t; idx < 64 * 128; idx += 512) {
            int kk = idx & 127, row = idx >> 7;
            a_s[kk * 68 + row] = g_hs[(base + row) * DST + kc * 128 + kk];
        }
        __syncthreads();

#pragma unroll 4
        for (int k = 0; k < 128; k++) {
            const float* wr = w_s + k * 132 + tx;
            U64F p0, p1;
            p0.f.x = wr[0];  p0.f.y = wr[32];
            p1.f.x = wr[64]; p1.f.y = wr[96];
            F4U av; av.f4 = *(const float4*)(a_s + k * 68 + lb0);
            float as4[4] = {av.f4.x, av.f4.y, av.f4.z, av.f4.w};
#pragma unroll
            for (int b = 0; b < 4; b++) {
                U64F d2; d2.f.x = as4[b]; d2.f.y = as4[b];
                ffma2(acc[0][b], p0.u, d2.u);
                ffma2(acc[1][b], p1.u, d2.u);
            }
        }
    }

    float bias[4];
#pragma unroll
    for (int j = 0; j < 4; j++) bias[j] = bfc[tx + 32 * j];

#pragma unroll
    for (int b = 0; b < 4; b++) {
        float* yp = y + (base + lb0 + b) * DIN + tx;
        U64F u0, u1; u0.u = acc[0][b]; u1.u = acc[1][b];
        yp[0]  = tanhf(u0.f.x + bias[0]);
        yp[32] = tanhf(u0.f.y + bias[1]);
        yp[64] = tanhf(u1.f.x + bias[2]);
        yp[96] = tanhf(u1.f.y + bias[3]);
    }
}

// ---------------------------------------------------------------------------
extern "C" void kernel_launch(void* const* d_in, const int* in_sizes, int n_in,
                              void* d_out, int out_size) {
    const float* x   = (const float*)d_in[0];
    const float* Wih = (const float*)d_in[1];
    const float* Whh = (const float*)d_in[2];
    const float* bih = (const float*)d_in[3];
    const float* bhh = (const float*)d_in[4];
    const float* Wfc = (const float*)d_in[5];
    const float* bfc = (const float*)d_in[6];
    float* y = (float*)d_out;

    cudaFuncSetAttribute(k_pre, cudaFuncAttributeMaxDynamicSharedMemorySize, PRE_SMEM);
    cudaFuncSetAttribute(k_out, cudaFuncAttributeMaxDynamicSharedMemorySize, OUT_SMEM);

    k_xT<<<dim3(L_SEQ / 32, (B_SZ * DIN) / 32), 256>>>(x);
    k_pre<<<dim3(L_SEQ / 2, 2), 512, PRE_SMEM>>>(Wih, bih, bhh);
    k_rnn<<<128, 576>>>(Whh);
    k_out<<<(L_SEQ * B_SZ) / 64, 512, OUT_SMEM>>>(Wfc, bfc, y);
}

// round 10
// speedup vs baseline: 1.6213x; 1.6213x over previous
#include <cuda_runtime.h>
#include <math.h>
#include <stdint.h>

// Problem constants
#define L_SEQ 2048
#define B_SZ  32
#define DIN   128
#define DST   512
#define NB4   4      // batches per cluster

// Scratch (device globals per allocation rules)
__device__ float g_pre[L_SEQ * B_SZ * DST];   // [l][b][h]   128 MB
__device__ float g_hs [L_SEQ * B_SZ * DST];   // [l][b][h]   128 MB
__device__ float g_xT [L_SEQ * B_SZ * DIN];   // [l][b][d]    32 MB

union F4U  { float4 f4; ulonglong2 u2; };
union U64F { unsigned long long u; float2 f; };

__device__ __forceinline__ void ffma2(unsigned long long& acc,
                                      unsigned long long a,
                                      unsigned long long b) {
    asm volatile("fma.rn.f32x2 %0, %1, %2, %0;" : "+l"(acc) : "l"(a), "l"(b));
}

__device__ __forceinline__ uint32_t smem_u32(const void* p) {
    return (uint32_t)__cvta_generic_to_shared(p);
}

// Fast tanh for the recurrent chain: MUFU.EX2-based, ~1e-7 abs error.
__device__ __forceinline__ float ftanh(float x) {
    float e = __expf(2.0f * x);
    return (e - 1.0f) / (e + 1.0f);
}

__device__ __forceinline__ void mbar_wait_cluster(uint32_t addr, uint32_t parity) {
    asm volatile(
        "{\n\t"
        ".reg .pred P;\n\t"
        "WAIT%=:\n\t"
        "mbarrier.try_wait.parity.acquire.cluster.shared::cta.b64 P, [%0], %1, 0x989680;\n\t"
        "@P bra DONE%=;\n\t"
        "bra WAIT%=;\n\t"
        "DONE%=:\n\t"
        "}\n"
        :: "r"(addr), "r"(parity) : "memory");
}

// ---------------------------------------------------------------------------
// Kernel 0: transpose x[b][d][l] -> xT[l][b*128+d].
// ---------------------------------------------------------------------------
__global__ void __launch_bounds__(256) k_xT(const float* __restrict__ x) {
    __shared__ float sm[32 * 33];
    const int l0  = blockIdx.x * 32;
    const int bd0 = blockIdx.y * 32;
    const int t   = threadIdx.x;
    for (int i = t; i < 1024; i += 256) {
        int r = i >> 5, c = i & 31;
        sm[r * 33 + c] = x[(size_t)(bd0 + r) * L_SEQ + l0 + c];
    }
    __syncthreads();
    for (int i = t; i < 1024; i += 256) {
        int r = i >> 5, c = i & 31;
        g_xT[(size_t)(l0 + r) * (B_SZ * DIN) + bd0 + c] = sm[c * 33 + r];
    }
}

// ---------------------------------------------------------------------------
// Kernel 1: pre[l][b][h]. 2 timesteps per block (W staged once).
// ---------------------------------------------------------------------------
#define PRE_SMEM ((128 * 257 + 128 * 36) * 4)

__global__ void __launch_bounds__(512) k_pre(const float* __restrict__ Wih,
                                             const float* __restrict__ bih,
                                             const float* __restrict__ bhh) {
    extern __shared__ float sm[];
    float* w_s = sm;               // [128 d][257]
    float* x_s = sm + 128 * 257;   // [128 d][36]

    const int lbase = blockIdx.x * 2;
    const int h0 = blockIdx.y * 256;
    const int t  = threadIdx.x;

    for (int idx = t; idx < 256 * 128; idx += 512) {
        int d = idx & 127, hh = idx >> 7;
        w_s[d * 257 + hh] = Wih[(size_t)(h0 + hh) * DIN + d];
    }

    const int tx = t & 63;
    const int b0 = (t >> 6) * 4;

    float bias[4];
#pragma unroll
    for (int j = 0; j < 4; j++)
        bias[j] = bih[h0 + tx + 64 * j] + bhh[h0 + tx + 64 * j];

    for (int l2 = 0; l2 < 2; l2++) {
        const int l = lbase + l2;
        __syncthreads();   // w_s ready (iter 0) / x_s consumers done (iter 1)
        for (int idx = t; idx < B_SZ * DIN; idx += 512) {
            int d = idx & 127, b = idx >> 7;
            x_s[d * 36 + b] = g_xT[(size_t)l * (B_SZ * DIN) + b * DIN + d];
        }
        __syncthreads();

        unsigned long long acc[2][4];
#pragma unroll
        for (int m = 0; m < 2; m++)
#pragma unroll
            for (int b = 0; b < 4; b++) acc[m][b] = 0ull;

#pragma unroll 4
        for (int k = 0; k < 128; k++) {
            const float* wr = w_s + k * 257 + tx;
            U64F p0, p1;
            p0.f.x = wr[0];   p0.f.y = wr[64];
            p1.f.x = wr[128]; p1.f.y = wr[192];
            F4U xv; xv.f4 = *(const float4*)(x_s + k * 36 + b0);
            float xs[4] = {xv.f4.x, xv.f4.y, xv.f4.z, xv.f4.w};
#pragma unroll
            for (int b = 0; b < 4; b++) {
                U64F d2; d2.f.x = xs[b]; d2.f.y = xs[b];
                ffma2(acc[0][b], p0.u, d2.u);
                ffma2(acc[1][b], p1.u, d2.u);
            }
        }

#pragma unroll
        for (int b = 0; b < 4; b++) {
            float* pr = g_pre + ((size_t)l * B_SZ + b0 + b) * DST + h0 + tx;
            U64F u0, u1; u0.u = acc[0][b]; u1.u = acc[1][b];
            pr[0]   = u0.f.x + bias[0];
            pr[64]  = u0.f.y + bias[1];
            pr[128] = u1.f.x + bias[2];
            pr[192] = u1.f.y + bias[3];
        }
    }
}

// ---------------------------------------------------------------------------
// Kernel 2: recurrent scan. 8 clusters x 8 CTAs x 640 threads; 4 batches =
// 4 pipelined sync domains (R8 skeleton, proven). Per-source mbarriers
// [batch][slot][src] count=1; TRYWAIT HW-sleep waits. Tail lane u owns rows
// 2u,2u+1: 64-bit g_pre/g_hs accesses, 8 packed 64-bit DSMEM pushes,
// __syncwarp ordering, fast tanh.
// ---------------------------------------------------------------------------
__global__ void __launch_bounds__(640, 1) __cluster_dims__(8, 1, 1)
k_rnn(const float* __restrict__ Whh) {
    __shared__ float hbuf[2][NB4 * DST];     // 16 KB exchange buffers
    __shared__ float red[2][NB4][64][9];     // 18 KB partials, step-parity buffered
    __shared__ __align__(8) unsigned long long barr[NB4][2][8]; // [b][slot][src]

    const int t    = threadIdx.x;
    const int warp = t >> 5;
    const int lane = t & 31;
    uint32_t rank;
    asm("mov.u32 %0, %%cluster_ctarank;" : "=r"(rank));
    const int cl = blockIdx.x >> 3;          // cluster id 0..7

    // compute-warp constants + register W
    const int rg  = warp & 1;
    const int kw  = warp >> 1;               // K slice / source CTA 0..7
    const int row = rg * 32 + lane;          // local row 0..63
    const int ks  = kw * 64;
    F4U w[16];
    if (t < 512) {
        const float4* wp = (const float4*)(Whh + (size_t)(rank * 64 + row) * DST + ks);
#pragma unroll
        for (int i = 0; i < 16; i++) w[i].f4 = wp[i];
    }

    // h_{-1} = 0 lives in parity buffer 1
    for (int i = t; i < NB4 * DST; i += 640) hbuf[1][i] = 0.f;

    uint32_t bar0 = smem_u32(&barr[0][0][0]);
    if (t == 0) {
        for (int i = 0; i < NB4 * 2 * 8; i++)
            asm volatile("mbarrier.init.shared.b64 [%0], %1;"
                         :: "r"(bar0 + 8u * i), "r"(1u) : "memory");
        asm volatile("fence.mbarrier_init.release.cluster;" ::: "memory");
    }
    __syncthreads();
    asm volatile("barrier.cluster.arrive.aligned;" ::: "memory");
    asm volatile("barrier.cluster.wait.aligned;" ::: "memory");

    const uint32_t hbase = smem_u32(&hbuf[0][0]);
    uint32_t peer_h[8];
#pragma unroll
    for (int p = 0; p < 8; p++)
        asm("mapa.shared::cluster.u32 %0, %1, %2;" : "=r"(peer_h[p]) : "r"(hbase), "r"(p));

    if (t < 512) {
        // ================= COMPUTE WARPS =================
        for (int l = 0; l < L_SEQ; l++) {
            const int prev = (l & 1) ^ 1;
            const int rbuf = l & 1;
            const uint32_t wslot = (uint32_t)((l - 1) & 1);
            const uint32_t wpar  = (uint32_t)(((l - 1) >> 1) & 1);
            const float* hbp = hbuf[prev];
            const uint32_t srcoff = 8u * (wslot * 8u + (uint32_t)kw);

#pragma unroll
            for (int b = 0; b < NB4; b++) {
                if (l > 0)
                    mbar_wait_cluster(bar0 + (uint32_t)(b * 128) + srcoff, wpar);
                const float4* hp = (const float4*)(hbp + b * DST + ks);
                unsigned long long a0 = 0ull, a1 = 0ull;
#pragma unroll
                for (int i = 0; i < 16; i++) {
                    F4U hv; hv.f4 = hp[i];      // broadcast LDS
                    ffma2(a0, hv.u2.x, w[i].u2.x);
                    ffma2(a1, hv.u2.y, w[i].u2.y);
                }
                U64F u0, u1; u0.u = a0; u1.u = a1;
                red[rbuf][b][row][kw] = u0.f.x + u0.f.y + u1.f.x + u1.f.y;
                asm volatile("bar.arrive %0, 544;"
                             :: "r"(1 + b * 2 + (l & 1)) : "memory");
            }
        }
    } else {
        // ================= TAIL WARPS (one per batch) =================
        const int tb = warp - 16;               // my batch 0..3
        const int u  = lane;                    // rows 2u, 2u+1 (contiguous)
        const size_t oi0 = (size_t)(cl * NB4 + tb) * DST + rank * 64 + 2 * u;
        const uint32_t po0 = (uint32_t)((tb * DST + (int)rank * 64 + 2 * u) * 4);

        for (int l = 0; l < L_SEQ; l++) {
            const int cur  = l & 1;
            const int rbuf = l & 1;
            float2 pv = *(const float2*)(g_pre + (size_t)l * (B_SZ * DST) + oi0);

            asm volatile("bar.sync %0, 544;"
                         :: "r"(1 + tb * 2 + (l & 1)) : "memory");

            float s0 = pv.x, s1 = pv.y;
#pragma unroll
            for (int k2 = 0; k2 < 8; k2++) {
                s0 += red[rbuf][tb][2 * u][k2];
                s1 += red[rbuf][tb][2 * u + 1][k2];
            }
            U64F hv2; hv2.f.x = ftanh(s0); hv2.f.y = ftanh(s1);
            *(float2*)(g_hs + (size_t)l * (B_SZ * DST) + oi0) = hv2.f;

            if (l < L_SEQ - 1) {
                uint32_t off0 = (uint32_t)(cur * NB4 * DST * 4) + po0;
#pragma unroll
                for (int p = 0; p < 8; p++)
                    asm volatile("st.shared::cluster.u64 [%0], %1;"
                                 :: "r"(peer_h[p] + off0), "l"(hv2.u) : "memory");
                __syncwarp();   // order this warp's pushes before the arrives
                if (u < 8) {
                    uint32_t local = bar0 + (uint32_t)(tb * 128)
                                   + 8u * ((uint32_t)cur * 8u + rank);
                    uint32_t ra;
                    asm("mapa.shared::cluster.u32 %0, %1, %2;"
                        : "=r"(ra) : "r"(local), "r"(u));
                    asm volatile("mbarrier.arrive.release.cluster.shared::cluster.b64 _, [%0];"
                                 :: "r"(ra) : "memory");
                }
            }
        }
    }

    // No CTA may exit while peers could still touch its smem.
    asm volatile("barrier.cluster.arrive.aligned;" ::: "memory");
    asm volatile("barrier.cluster.wait.aligned;" ::: "memory");
}

// ---------------------------------------------------------------------------
// Kernel 3: y[lb][o] = tanh(b_fc[o] + sum_k hs[lb][k] * W_fc[o][k])
// ---------------------------------------------------------------------------
#define OUT_SMEM ((128 * 132 + 128 * 68) * 4)

__global__ void __launch_bounds__(512) k_out(const float* __restrict__ Wfc,
                                             const float* __restrict__ bfc,
                                             float* __restrict__ y) {
    extern __shared__ float sm[];
    float* w_s = sm;               // [128 kk][132]
    float* a_s = sm + 128 * 132;   // [128 kk][68]

    const int t = threadIdx.x;
    const size_t base = (size_t)blockIdx.x * 64;
    const int tx  = t & 31;
    const int lb0 = (t >> 5) * 4;

    unsigned long long acc[2][4];
#pragma unroll
    for (int m = 0; m < 2; m++)
#pragma unroll
        for (int b = 0; b < 4; b++) acc[m][b] = 0ull;

    for (int kc = 0; kc < 4; kc++) {
        __syncthreads();
        for (int idx = t; idx < 128 * 128; idx += 512) {
            int kk = idx & 127, o = idx >> 7;
            w_s[kk * 132 + o] = Wfc[(size_t)o * DST + kc * 128 + kk];
        }
        for (int idx = t; idx < 64 * 128; idx += 512) {
            int kk = idx & 127, row = idx >> 7;
            a_s[kk * 68 + row] = g_hs[(base + row) * DST + kc * 128 + kk];
        }
        __syncthreads();

#pragma unroll 4
        for (int k = 0; k < 128; k++) {
            const float* wr = w_s + k * 132 + tx;
            U64F p0, p1;
            p0.f.x = wr[0];  p0.f.y = wr[32];
            p1.f.x = wr[64]; p1.f.y = wr[96];
            F4U av; av.f4 = *(const float4*)(a_s + k * 68 + lb0);
            float as4[4] = {av.f4.x, av.f4.y, av.f4.z, av.f4.w};
#pragma unroll
            for (int b = 0; b < 4; b++) {
                U64F d2; d2.f.x = as4[b]; d2.f.y = as4[b];
                ffma2(acc[0][b], p0.u, d2.u);
                ffma2(acc[1][b], p1.u, d2.u);
            }
        }
    }

    float bias[4];
#pragma unroll
    for (int j = 0; j < 4; j++) bias[j] = bfc[tx + 32 * j];

#pragma unroll
    for (int b = 0; b < 4; b++) {
        float* yp = y + (base + lb0 + b) * DIN + tx;
        U64F u0, u1; u0.u = acc[0][b]; u1.u = acc[1][b];
        yp[0]  = tanhf(u0.f.x + bias[0]);
        yp[32] = tanhf(u0.f.y + bias[1]);
        yp[64] = tanhf(u1.f.x + bias[2]);
        yp[96] = tanhf(u1.f.y + bias[3]);
    }
}

// ---------------------------------------------------------------------------
extern "C" void kernel_launch(void* const* d_in, const int* in_sizes, int n_in,
                              void* d_out, int out_size) {
    const float* x   = (const float*)d_in[0];
    const float* Wih = (const float*)d_in[1];
    const float* Whh = (const float*)d_in[2];
    const float* bih = (const float*)d_in[3];
    const float* bhh = (const float*)d_in[4];
    const float* Wfc = (const float*)d_in[5];
    const float* bfc = (const float*)d_in[6];
    float* y = (float*)d_out;

    cudaFuncSetAttribute(k_pre, cudaFuncAttributeMaxDynamicSharedMemorySize, PRE_SMEM);
    cudaFuncSetAttribute(k_out, cudaFuncAttributeMaxDynamicSharedMemorySize, OUT_SMEM);

    k_xT<<<dim3(L_SEQ / 32, (B_SZ * DIN) / 32), 256>>>(x);
    k_pre<<<dim3(L_SEQ / 2, 2), 512, PRE_SMEM>>>(Wih, bih, bhh);
    k_rnn<<<64, 640>>>(Whh);
    k_out<<<(L_SEQ * B_SZ) / 64, 512, OUT_SMEM>>>(Wfc, bfc, y);
}